// round 1
// baseline (speedup 1.0000x reference)
#include <cuda_runtime.h>
#include <math_constants.h>

// Problem constants
#define Bsz   4
#define Ssz   2048
#define Dsz   1024
#define Hn    16
#define HDim  64
#define Mrows (Bsz * Ssz)   // 8192

// Scratch (static device globals -- no allocation at runtime)
__device__ float g_qh[Mrows * Dsz];
__device__ float g_kh[Mrows * Dsz];
__device__ float g_vh[Mrows * Dsz];
__device__ float g_hidden[Mrows * Dsz];

// ---------------------------------------------------------------------------
// GEMM: C[M,N] = X[M,K] @ W[N,K]^T + bias[N]
// M=8192, N=1024, K=1024. BM=128, BN=64, BK=16. 256 threads, 8x4 per thread.
// Both X and W are K-contiguous row-major -> coalesced float4 global loads.
// Smem tiles stored transposed [BK][BM] so compute reads are float4.
// ---------------------------------------------------------------------------
__global__ __launch_bounds__(256) void gemm_xwt_kernel(
    const float* __restrict__ X, const float* __restrict__ W,
    const float* __restrict__ bias, float* __restrict__ C)
{
    __shared__ float Xs[16][132];   // pad 4 to reduce store conflicts, keep 16B align
    __shared__ float Ws[16][68];

    const int tx = threadIdx.x & 15;      // 0..15 -> N direction (4 cols each)
    const int ty = threadIdx.x >> 4;      // 0..15 -> M direction (8 rows each)
    const int m0 = blockIdx.y * 128;
    const int n0 = blockIdx.x * 64;

    float acc[8][4];
#pragma unroll
    for (int i = 0; i < 8; i++)
#pragma unroll
        for (int j = 0; j < 4; j++) acc[i][j] = 0.f;

    for (int kt = 0; kt < 1024; kt += 16) {
        // Load X tile: 128x16 floats = 512 float4, 2 per thread
#pragma unroll
        for (int it = 0; it < 2; it++) {
            int idx = threadIdx.x + it * 256;
            int row = idx >> 2;
            int kq  = (idx & 3) * 4;
            float4 v = *(const float4*)&X[(size_t)(m0 + row) * 1024 + kt + kq];
            Xs[kq + 0][row] = v.x;
            Xs[kq + 1][row] = v.y;
            Xs[kq + 2][row] = v.z;
            Xs[kq + 3][row] = v.w;
        }
        // Load W tile: 64x16 floats = 256 float4, 1 per thread
        {
            int idx = threadIdx.x;
            int row = idx >> 2;
            int kq  = (idx & 3) * 4;
            float4 v = *(const float4*)&W[(size_t)(n0 + row) * 1024 + kt + kq];
            Ws[kq + 0][row] = v.x;
            Ws[kq + 1][row] = v.y;
            Ws[kq + 2][row] = v.z;
            Ws[kq + 3][row] = v.w;
        }
        __syncthreads();

#pragma unroll
        for (int k = 0; k < 16; k++) {
            float4 a0 = *(const float4*)&Xs[k][ty * 8];
            float4 a1 = *(const float4*)&Xs[k][ty * 8 + 4];
            float4 b0 = *(const float4*)&Ws[k][tx * 4];
            float a[8] = {a0.x, a0.y, a0.z, a0.w, a1.x, a1.y, a1.z, a1.w};
            float b[4] = {b0.x, b0.y, b0.z, b0.w};
#pragma unroll
            for (int i = 0; i < 8; i++)
#pragma unroll
                for (int j = 0; j < 4; j++)
                    acc[i][j] += a[i] * b[j];
        }
        __syncthreads();
    }

    float4 bia = *(const float4*)&bias[n0 + tx * 4];
#pragma unroll
    for (int i = 0; i < 8; i++) {
        float4 o;
        o.x = acc[i][0] + bia.x;
        o.y = acc[i][1] + bia.y;
        o.z = acc[i][2] + bia.z;
        o.w = acc[i][3] + bia.w;
        *(float4*)&C[(size_t)(m0 + ty * 8 + i) * 1024 + n0 + tx * 4] = o;
    }
}

// ---------------------------------------------------------------------------
// Fused attention (flash-style, fp32). One block = 128 query rows of one
// (batch, head). Each thread owns one query row: q[64] and acc[64] in regs,
// K/V 64x64 tiles staged in smem, read as broadcast float4.
// Mask semantics: mask[b,q]==0 -> all scores of that query row = -1e9
// (softmax of constant row -> uniform -> mean of V), matching the reference.
// ---------------------------------------------------------------------------
__global__ __launch_bounds__(128) void attn_kernel(
    const float* __restrict__ qh, const float* __restrict__ kh,
    const float* __restrict__ vh, const int* __restrict__ mask,
    float* __restrict__ hidden)
{
    const int bh = blockIdx.y;          // 0..63
    const int b  = bh >> 4;
    const int h  = bh & 15;
    const int t  = threadIdx.x;         // 0..127
    const int qrow = blockIdx.x * 128 + t;

    __shared__ float4 ks4[64 * 16];
    __shared__ float4 vs4[64 * 16];

    float q[64], acc[64];
    const float* qptr = &qh[((size_t)(b * 2048 + qrow)) * 1024 + h * 64];
#pragma unroll
    for (int d4 = 0; d4 < 16; d4++) {
        float4 v = *(const float4*)&qptr[d4 * 4];
        q[d4 * 4 + 0] = v.x * 0.125f;   // fold 1/sqrt(64) into q
        q[d4 * 4 + 1] = v.y * 0.125f;
        q[d4 * 4 + 2] = v.z * 0.125f;
        q[d4 * 4 + 3] = v.w * 0.125f;
    }
#pragma unroll
    for (int d = 0; d < 64; d++) acc[d] = 0.f;

    const bool masked = (mask[b * 2048 + qrow] == 0);
    float m = -CUDART_INF_F;
    float l = 0.f;

    for (int kt = 0; kt < 2048; kt += 64) {
        // Stage K and V tiles: 64 rows x 16 float4 each; 8 float4 per thread each.
#pragma unroll
        for (int i = 0; i < 8; i++) {
            int idx = t + i * 128;
            int row = idx >> 4;
            int c   = idx & 15;
            size_t g = ((size_t)(b * 2048 + kt + row)) * 1024 + h * 64 + c * 4;
            ks4[idx] = *(const float4*)&kh[g];
            vs4[idx] = *(const float4*)&vh[g];
        }
        __syncthreads();

#pragma unroll 2
        for (int j = 0; j < 64; j++) {
            float s = 0.f;
#pragma unroll
            for (int d4 = 0; d4 < 16; d4++) {
                float4 kk = ks4[j * 16 + d4];
                s += q[d4 * 4 + 0] * kk.x + q[d4 * 4 + 1] * kk.y
                   + q[d4 * 4 + 2] * kk.z + q[d4 * 4 + 3] * kk.w;
            }
            if (masked) s = -1e9f;
            if (s > m) {                      // rare after warmup
                float corr = __expf(m - s);   // expf(-inf)=0 handles first iter
                l *= corr;
#pragma unroll
                for (int d = 0; d < 64; d++) acc[d] *= corr;
                m = s;
            }
            float p = __expf(s - m);
            l += p;
#pragma unroll
            for (int d4 = 0; d4 < 16; d4++) {
                float4 vv = vs4[j * 16 + d4];
                acc[d4 * 4 + 0] += p * vv.x;
                acc[d4 * 4 + 1] += p * vv.y;
                acc[d4 * 4 + 2] += p * vv.z;
                acc[d4 * 4 + 3] += p * vv.w;
            }
        }
        __syncthreads();
    }

    const float inv = 1.f / l;
    float* op = &hidden[((size_t)(b * 2048 + qrow)) * 1024 + h * 64];
#pragma unroll
    for (int d4 = 0; d4 < 16; d4++) {
        float4 o;
        o.x = acc[d4 * 4 + 0] * inv;
        o.y = acc[d4 * 4 + 1] * inv;
        o.z = acc[d4 * 4 + 2] * inv;
        o.w = acc[d4 * 4 + 3] * inv;
        *(float4*)&op[d4 * 4] = o;
    }
}

// ---------------------------------------------------------------------------
// Launch
// ---------------------------------------------------------------------------
extern "C" void kernel_launch(void* const* d_in, const int* in_sizes, int n_in,
                              void* d_out, int out_size)
{
    const float* q    = (const float*)d_in[0];
    const float* k    = (const float*)d_in[1];
    const float* v    = (const float*)d_in[2];
    const float* Wq   = (const float*)d_in[3];
    const float* bq   = (const float*)d_in[4];
    const float* Wk   = (const float*)d_in[5];
    const float* bk   = (const float*)d_in[6];
    const float* Wv   = (const float*)d_in[7];
    const float* bv   = (const float*)d_in[8];
    const float* Wo   = (const float*)d_in[9];
    const float* bo   = (const float*)d_in[10];
    const int*   mask = (const int*)d_in[11];
    float* out = (float*)d_out;

    float *qh, *kh, *vh, *hid;
    cudaGetSymbolAddress((void**)&qh,  g_qh);
    cudaGetSymbolAddress((void**)&kh,  g_kh);
    cudaGetSymbolAddress((void**)&vh,  g_vh);
    cudaGetSymbolAddress((void**)&hid, g_hidden);

    dim3 ggrid(1024 / 64, Mrows / 128);   // (16, 64)
    gemm_xwt_kernel<<<ggrid, 256>>>(q, Wq, bq, qh);
    gemm_xwt_kernel<<<ggrid, 256>>>(k, Wk, bk, kh);
    gemm_xwt_kernel<<<ggrid, 256>>>(v, Wv, bv, vh);

    dim3 agrid(Ssz / 128, Bsz * Hn);      // (16, 64)
    attn_kernel<<<agrid, 128>>>(qh, kh, vh, mask, hid);

    gemm_xwt_kernel<<<ggrid, 256>>>(hid, Wo, bo, out);
}

// round 2
// speedup vs baseline: 2.8167x; 2.8167x over previous
#include <cuda_runtime.h>
#include <cuda_bf16.h>
#include <math_constants.h>

// Problem constants
#define Bsz   4
#define Ssz   2048
#define Dsz   1024
#define Hn    16
#define HDim  64
#define Mrows (Bsz * Ssz)   // 8192

// Scratch (static device globals -- no allocation at runtime)
__device__ float g_qh[Mrows * Dsz];
__device__ float g_kh[Mrows * Dsz];
__device__ float g_vh[Mrows * Dsz];
__device__ float g_hidden[Mrows * Dsz];

// ---------------------------------------------------------------------------
// MMA / ldmatrix helpers (sm_80+ mma.sync path, runs on Blackwell HMMA)
// ---------------------------------------------------------------------------
__device__ __forceinline__ unsigned smem_u32(const void* p) {
    return (unsigned)__cvta_generic_to_shared(p);
}

__device__ __forceinline__ void ldm_x4(unsigned& r0, unsigned& r1, unsigned& r2, unsigned& r3,
                                       unsigned addr) {
    asm volatile("ldmatrix.sync.aligned.m8n8.x4.shared.b16 {%0,%1,%2,%3}, [%4];"
                 : "=r"(r0), "=r"(r1), "=r"(r2), "=r"(r3) : "r"(addr));
}

__device__ __forceinline__ void ldm_x4_t(unsigned& r0, unsigned& r1, unsigned& r2, unsigned& r3,
                                         unsigned addr) {
    asm volatile("ldmatrix.sync.aligned.m8n8.x4.trans.shared.b16 {%0,%1,%2,%3}, [%4];"
                 : "=r"(r0), "=r"(r1), "=r"(r2), "=r"(r3) : "r"(addr));
}

__device__ __forceinline__ void mma_bf16(float* c, const unsigned* a, unsigned b0, unsigned b1) {
    asm volatile(
        "mma.sync.aligned.m16n8k16.row.col.f32.bf16.bf16.f32 "
        "{%0,%1,%2,%3}, {%4,%5,%6,%7}, {%8,%9}, {%0,%1,%2,%3};"
        : "+f"(c[0]), "+f"(c[1]), "+f"(c[2]), "+f"(c[3])
        : "r"(a[0]), "r"(a[1]), "r"(a[2]), "r"(a[3]), "r"(b0), "r"(b1));
}

// Convert 4 fp32 -> hi/lo bf16 split, store as two bf16x2 each
__device__ __forceinline__ void cvt_split_store(__nv_bfloat16* hp, __nv_bfloat16* lp, float4 v) {
    __nv_bfloat16 h0 = __float2bfloat16(v.x);
    __nv_bfloat16 h1 = __float2bfloat16(v.y);
    __nv_bfloat16 h2 = __float2bfloat16(v.z);
    __nv_bfloat16 h3 = __float2bfloat16(v.w);
    __nv_bfloat16 l0 = __float2bfloat16(v.x - __bfloat162float(h0));
    __nv_bfloat16 l1 = __float2bfloat16(v.y - __bfloat162float(h1));
    __nv_bfloat16 l2 = __float2bfloat16(v.z - __bfloat162float(h2));
    __nv_bfloat16 l3 = __float2bfloat16(v.w - __bfloat162float(h3));
    __nv_bfloat162 hh01; hh01.x = h0; hh01.y = h1;
    __nv_bfloat162 hh23; hh23.x = h2; hh23.y = h3;
    __nv_bfloat162 ll01; ll01.x = l0; ll01.y = l1;
    __nv_bfloat162 ll23; ll23.x = l2; ll23.y = l3;
    *(__nv_bfloat162*)(hp)     = hh01;
    *(__nv_bfloat162*)(hp + 2) = hh23;
    *(__nv_bfloat162*)(lp)     = ll01;
    *(__nv_bfloat162*)(lp + 2) = ll23;
}

__device__ __forceinline__ unsigned pack_bf16(float a, float b) {
    __nv_bfloat162 h; h.x = __float2bfloat16(a); h.y = __float2bfloat16(b);
    return *(unsigned*)&h;
}

// ---------------------------------------------------------------------------
// GEMM: C[M,N] = X[M,K] @ W[N,K]^T + bias.  M=8192, N=K=1024.
// Block 128x128, 8 warps, warp tile 32x64. bf16 hi/lo split (3 MMAs / pair).
// ---------------------------------------------------------------------------
__global__ __launch_bounds__(256) void gemm_mma_kernel(
    const float* __restrict__ X, const float* __restrict__ W,
    const float* __restrict__ bias, float* __restrict__ C)
{
    __shared__ __nv_bfloat16 Xh[128][40];  // pad 32->40 (80B stride: ldmatrix conflict-free)
    __shared__ __nv_bfloat16 Xl[128][40];
    __shared__ __nv_bfloat16 Wh[128][40];
    __shared__ __nv_bfloat16 Wl[128][40];

    const int tid  = threadIdx.x;
    const int lane = tid & 31;
    const int wid  = tid >> 5;
    const int wm   = wid & 3;          // 0..3 (m)
    const int wn   = wid >> 2;         // 0..1 (n)
    const int m0   = blockIdx.y * 128;
    const int n0   = blockIdx.x * 128;
    const int lrow = lane & 15;
    const int lcol = (lane >> 4) * 8;

    float acc[2][8][4];
#pragma unroll
    for (int i = 0; i < 2; i++)
#pragma unroll
        for (int j = 0; j < 8; j++)
#pragma unroll
            for (int r = 0; r < 4; r++) acc[i][j][r] = 0.f;

    for (int k0 = 0; k0 < 1024; k0 += 32) {
        // Load + split X tile (128x32) and W tile (128x32): 1024 float4 each
#pragma unroll
        for (int i = 0; i < 4; i++) {
            int idx = tid + i * 256;
            int row = idx >> 3;
            int c4  = (idx & 7) * 4;
            float4 vx = *(const float4*)&X[(size_t)(m0 + row) * 1024 + k0 + c4];
            cvt_split_store(&Xh[row][c4], &Xl[row][c4], vx);
            float4 vw = *(const float4*)&W[(size_t)(n0 + row) * 1024 + k0 + c4];
            cvt_split_store(&Wh[row][c4], &Wl[row][c4], vw);
        }
        __syncthreads();

#pragma unroll
        for (int ks = 0; ks < 32; ks += 16) {
            unsigned ah[2][4], al[2][4];
#pragma unroll
            for (int mf = 0; mf < 2; mf++) {
                unsigned ra = smem_u32(&Xh[wm * 32 + mf * 16 + lrow][ks + lcol]);
                ldm_x4(ah[mf][0], ah[mf][1], ah[mf][2], ah[mf][3], ra);
                unsigned rl = smem_u32(&Xl[wm * 32 + mf * 16 + lrow][ks + lcol]);
                ldm_x4(al[mf][0], al[mf][1], al[mf][2], al[mf][3], rl);
            }
#pragma unroll
            for (int nf2 = 0; nf2 < 4; nf2++) {
                unsigned bh0, bh1, bh2, bh3, bl0, bl1, bl2, bl3;
                unsigned rb = smem_u32(&Wh[wn * 64 + nf2 * 16 + lrow][ks + lcol]);
                ldm_x4(bh0, bh1, bh2, bh3, rb);
                unsigned rc = smem_u32(&Wl[wn * 64 + nf2 * 16 + lrow][ks + lcol]);
                ldm_x4(bl0, bl1, bl2, bl3, rc);
                // frag j0 = nf2*2 -> (t0,t2) ; j0+1 -> (t1,t3)
#pragma unroll
                for (int mf = 0; mf < 2; mf++) {
                    mma_bf16(acc[mf][nf2 * 2],     ah[mf], bh0, bh2);
                    mma_bf16(acc[mf][nf2 * 2],     ah[mf], bl0, bl2);
                    mma_bf16(acc[mf][nf2 * 2],     al[mf], bh0, bh2);
                    mma_bf16(acc[mf][nf2 * 2 + 1], ah[mf], bh1, bh3);
                    mma_bf16(acc[mf][nf2 * 2 + 1], ah[mf], bl1, bl3);
                    mma_bf16(acc[mf][nf2 * 2 + 1], al[mf], bh1, bh3);
                }
            }
        }
        __syncthreads();
    }

    // Epilogue: bias + store
#pragma unroll
    for (int mf = 0; mf < 2; mf++) {
#pragma unroll
        for (int nf = 0; nf < 8; nf++) {
            int row = m0 + wm * 32 + mf * 16 + (lane >> 2);
            int col = n0 + wn * 64 + nf * 8 + (lane & 3) * 2;
            float b0v = bias[col], b1v = bias[col + 1];
            float2 o0 = {acc[mf][nf][0] + b0v, acc[mf][nf][1] + b1v};
            float2 o1 = {acc[mf][nf][2] + b0v, acc[mf][nf][3] + b1v};
            *(float2*)&C[(size_t)row * 1024 + col] = o0;
            *(float2*)&C[(size_t)(row + 8) * 1024 + col] = o1;
        }
    }
}

// ---------------------------------------------------------------------------
// Flash attention, tensor-core version. Block = 64 query rows of one (b,h),
// 4 warps x 16 rows. Q frags resident (hi/lo). K via ldmatrix, V via
// ldmatrix.trans. S-frag -> A-frag register reuse for P@V. Online softmax.
// ---------------------------------------------------------------------------
__global__ __launch_bounds__(128) void attn_mma_kernel(
    const float* __restrict__ qh, const float* __restrict__ kh,
    const float* __restrict__ vh, const int* __restrict__ mask,
    float* __restrict__ hidden)
{
    __shared__ __nv_bfloat16 Kh[64][72];  // 144B stride: ldmatrix conflict-free
    __shared__ __nv_bfloat16 Kl[64][72];
    __shared__ __nv_bfloat16 Vh[64][72];
    __shared__ __nv_bfloat16 Vl[64][72];

    const int tid  = threadIdx.x;
    const int lane = tid & 31;
    const int wid  = tid >> 5;
    const int bh   = blockIdx.y;
    const int b    = bh >> 4;
    const int h    = bh & 15;
    const int q0   = blockIdx.x * 64;
    const int lrow = lane & 15;
    const int lcol = (lane >> 4) * 8;

    // ---- Stage Q (scaled by 1/8) into Kh/Kl, then load resident frags ----
#pragma unroll
    for (int i = 0; i < 8; i++) {
        int idx = tid + i * 128;
        int row = idx >> 4;
        int c4  = (idx & 15) * 4;
        float4 v = *(const float4*)&qh[(size_t)(b * 2048 + q0 + row) * 1024 + h * 64 + c4];
        v.x *= 0.125f; v.y *= 0.125f; v.z *= 0.125f; v.w *= 0.125f;
        cvt_split_store(&Kh[row][c4], &Kl[row][c4], v);
    }
    __syncthreads();

    unsigned qfh[4][4], qfl[4][4];
#pragma unroll
    for (int ksd = 0; ksd < 4; ksd++) {
        unsigned ra = smem_u32(&Kh[wid * 16 + lrow][ksd * 16 + lcol]);
        ldm_x4(qfh[ksd][0], qfh[ksd][1], qfh[ksd][2], qfh[ksd][3], ra);
        unsigned rl = smem_u32(&Kl[wid * 16 + lrow][ksd * 16 + lcol]);
        ldm_x4(qfl[ksd][0], qfl[ksd][1], qfl[ksd][2], qfl[ksd][3], rl);
    }
    __syncthreads();

    const int row0 = q0 + wid * 16 + (lane >> 2);
    const bool msk0 = (mask[b * 2048 + row0] == 0);
    const bool msk1 = (mask[b * 2048 + row0 + 8] == 0);

    float m_i[2] = {-CUDART_INF_F, -CUDART_INF_F};
    float l_i[2] = {0.f, 0.f};
    float O[8][4];
#pragma unroll
    for (int j = 0; j < 8; j++)
#pragma unroll
        for (int r = 0; r < 4; r++) O[j][r] = 0.f;

    for (int kt = 0; kt < 2048; kt += 64) {
        // ---- Stage K & V tiles (64x64 each) ----
#pragma unroll
        for (int i = 0; i < 8; i++) {
            int idx = tid + i * 128;
            int row = idx >> 4;
            int c4  = (idx & 15) * 4;
            size_t g = (size_t)(b * 2048 + kt + row) * 1024 + h * 64 + c4;
            float4 vk = *(const float4*)&kh[g];
            cvt_split_store(&Kh[row][c4], &Kl[row][c4], vk);
            float4 vv = *(const float4*)&vh[g];
            cvt_split_store(&Vh[row][c4], &Vl[row][c4], vv);
        }
        __syncthreads();

        // ---- S = Q @ K^T  (16 rows x 64 keys per warp) ----
        float s[8][4];
#pragma unroll
        for (int j = 0; j < 8; j++)
#pragma unroll
            for (int r = 0; r < 4; r++) s[j][r] = 0.f;

#pragma unroll
        for (int ksd = 0; ksd < 4; ksd++) {
#pragma unroll
            for (int nf2 = 0; nf2 < 4; nf2++) {
                unsigned bh0, bh1, bh2, bh3, bl0, bl1, bl2, bl3;
                unsigned rb = smem_u32(&Kh[nf2 * 16 + lrow][ksd * 16 + lcol]);
                ldm_x4(bh0, bh1, bh2, bh3, rb);
                unsigned rc = smem_u32(&Kl[nf2 * 16 + lrow][ksd * 16 + lcol]);
                ldm_x4(bl0, bl1, bl2, bl3, rc);
                mma_bf16(s[nf2 * 2],     qfh[ksd], bh0, bh2);
                mma_bf16(s[nf2 * 2],     qfh[ksd], bl0, bl2);
                mma_bf16(s[nf2 * 2],     qfl[ksd], bh0, bh2);
                mma_bf16(s[nf2 * 2 + 1], qfh[ksd], bh1, bh3);
                mma_bf16(s[nf2 * 2 + 1], qfh[ksd], bl1, bl3);
                mma_bf16(s[nf2 * 2 + 1], qfl[ksd], bh1, bh3);
            }
        }

        // ---- mask (query rows) ----
        if (msk0) {
#pragma unroll
            for (int j = 0; j < 8; j++) { s[j][0] = -1e9f; s[j][1] = -1e9f; }
        }
        if (msk1) {
#pragma unroll
            for (int j = 0; j < 8; j++) { s[j][2] = -1e9f; s[j][3] = -1e9f; }
        }

        // ---- online softmax (rows r=lane/4 and r+8) ----
        float corr[2];
#pragma unroll
        for (int hf = 0; hf < 2; hf++) {
            float mx = -CUDART_INF_F;
#pragma unroll
            for (int j = 0; j < 8; j++)
                mx = fmaxf(mx, fmaxf(s[j][2 * hf], s[j][2 * hf + 1]));
            mx = fmaxf(mx, __shfl_xor_sync(0xffffffff, mx, 1));
            mx = fmaxf(mx, __shfl_xor_sync(0xffffffff, mx, 2));
            float m_new = fmaxf(m_i[hf], mx);
            corr[hf] = __expf(m_i[hf] - m_new);
            m_i[hf] = m_new;
            float rs = 0.f;
#pragma unroll
            for (int j = 0; j < 8; j++) {
                float p0 = __expf(s[j][2 * hf] - m_new);
                float p1 = __expf(s[j][2 * hf + 1] - m_new);
                s[j][2 * hf] = p0; s[j][2 * hf + 1] = p1;
                rs += p0 + p1;
            }
            rs += __shfl_xor_sync(0xffffffff, rs, 1);
            rs += __shfl_xor_sync(0xffffffff, rs, 2);
            l_i[hf] = l_i[hf] * corr[hf] + rs;
#pragma unroll
            for (int j = 0; j < 8; j++) {
                O[j][2 * hf]     *= corr[hf];
                O[j][2 * hf + 1] *= corr[hf];
            }
        }

        // ---- O += P @ V  (P from s regs, V via ldmatrix.trans) ----
#pragma unroll
        for (int kg = 0; kg < 4; kg++) {
            int j0 = kg * 2, j1 = kg * 2 + 1;
            unsigned a_hi[4], a_lo[4];
            a_hi[0] = pack_bf16(s[j0][0], s[j0][1]);
            a_hi[1] = pack_bf16(s[j0][2], s[j0][3]);
            a_hi[2] = pack_bf16(s[j1][0], s[j1][1]);
            a_hi[3] = pack_bf16(s[j1][2], s[j1][3]);
            // lo residues
            {
                __nv_bfloat162 t;
                t = *(__nv_bfloat162*)&a_hi[0];
                a_lo[0] = pack_bf16(s[j0][0] - __bfloat162float(t.x), s[j0][1] - __bfloat162float(t.y));
                t = *(__nv_bfloat162*)&a_hi[1];
                a_lo[1] = pack_bf16(s[j0][2] - __bfloat162float(t.x), s[j0][3] - __bfloat162float(t.y));
                t = *(__nv_bfloat162*)&a_hi[2];
                a_lo[2] = pack_bf16(s[j1][0] - __bfloat162float(t.x), s[j1][1] - __bfloat162float(t.y));
                t = *(__nv_bfloat162*)&a_hi[3];
                a_lo[3] = pack_bf16(s[j1][2] - __bfloat162float(t.x), s[j1][3] - __bfloat162float(t.y));
            }
#pragma unroll
            for (int nf2 = 0; nf2 < 4; nf2++) {
                unsigned vh0, vh1, vh2, vh3, vl0, vl1, vl2, vl3;
                unsigned rb = smem_u32(&Vh[kg * 16 + lrow][nf2 * 16 + lcol]);
                ldm_x4_t(vh0, vh1, vh2, vh3, rb);
                unsigned rc = smem_u32(&Vl[kg * 16 + lrow][nf2 * 16 + lcol]);
                ldm_x4_t(vl0, vl1, vl2, vl3, rc);
                // trans: fragA (d lo 8) = (t0,t1); fragB (d hi 8) = (t2,t3)
                mma_bf16(O[nf2 * 2],     a_hi, vh0, vh1);
                mma_bf16(O[nf2 * 2],     a_hi, vl0, vl1);
                mma_bf16(O[nf2 * 2],     a_lo, vh0, vh1);
                mma_bf16(O[nf2 * 2 + 1], a_hi, vh2, vh3);
                mma_bf16(O[nf2 * 2 + 1], a_hi, vl2, vl3);
                mma_bf16(O[nf2 * 2 + 1], a_lo, vh2, vh3);
            }
        }
        __syncthreads();
    }

    // ---- Epilogue ----
    float inv0 = 1.f / l_i[0];
    float inv1 = 1.f / l_i[1];
#pragma unroll
    for (int nf = 0; nf < 8; nf++) {
        int col = h * 64 + nf * 8 + (lane & 3) * 2;
        float2 o0 = {O[nf][0] * inv0, O[nf][1] * inv0};
        float2 o1 = {O[nf][2] * inv1, O[nf][3] * inv1};
        *(float2*)&hidden[(size_t)(b * 2048 + row0) * 1024 + col] = o0;
        *(float2*)&hidden[(size_t)(b * 2048 + row0 + 8) * 1024 + col] = o1;
    }
}

// ---------------------------------------------------------------------------
// Launch
// ---------------------------------------------------------------------------
extern "C" void kernel_launch(void* const* d_in, const int* in_sizes, int n_in,
                              void* d_out, int out_size)
{
    const float* q    = (const float*)d_in[0];
    const float* k    = (const float*)d_in[1];
    const float* v    = (const float*)d_in[2];
    const float* Wq   = (const float*)d_in[3];
    const float* bq   = (const float*)d_in[4];
    const float* Wk   = (const float*)d_in[5];
    const float* bk   = (const float*)d_in[6];
    const float* Wv   = (const float*)d_in[7];
    const float* bv   = (const float*)d_in[8];
    const float* Wo   = (const float*)d_in[9];
    const float* bo   = (const float*)d_in[10];
    const int*   mask = (const int*)d_in[11];
    float* out = (float*)d_out;

    float *qhp, *khp, *vhp, *hid;
    cudaGetSymbolAddress((void**)&qhp, g_qh);
    cudaGetSymbolAddress((void**)&khp, g_kh);
    cudaGetSymbolAddress((void**)&vhp, g_vh);
    cudaGetSymbolAddress((void**)&hid, g_hidden);

    dim3 ggrid(1024 / 128, Mrows / 128);   // (8, 64)
    gemm_mma_kernel<<<ggrid, 256>>>(q, Wq, bq, qhp);
    gemm_mma_kernel<<<ggrid, 256>>>(k, Wk, bk, khp);
    gemm_mma_kernel<<<ggrid, 256>>>(v, Wv, bv, vhp);

    dim3 agrid(Ssz / 64, Bsz * Hn);        // (32, 64)
    attn_mma_kernel<<<agrid, 128>>>(qhp, khp, vhp, mask, hid);

    gemm_mma_kernel<<<ggrid, 256>>>(hid, Wo, bo, out);
}